// round 7
// baseline (speedup 1.0000x reference)
#include <cuda_runtime.h>
#include <cstdint>
#include <math.h>

// Problem constants
#define kD    1024
#define kE    256
#define kNE   2048
#define kCH   4
#define kM1   16384
#define kMR   65536
#define kNT   16            // col tiles (2048/128)

// -------- scratch (static device globals; no allocations) --------
__device__ float  g_cz[(size_t)kM1 * kD];          // 64 MB
__device__ float  g_P[(size_t)kCH * kNE * kD];     // 32 MB
__device__ float  g_tmax[(size_t)kMR * kNT];       // 4 MB
__device__ float  g_tmin[(size_t)kMR * kNT];       // 4 MB
__device__ float  g_esq[kNE];
__device__ float  g_czsq[kMR];
__device__ int    g_idx[kMR];
__device__ double g_part[4096];

// ------------------------- f32x2 packed FMA helpers -------------------------
#define FFMA2(d, a, b) asm("fma.rn.f32x2 %0, %1, %2, %0;" : "+l"(d) : "l"(a), "l"(b))
#define PACK2(d, f)    asm("mov.b64 %0, {%1, %1};" : "=l"(d) : "r"(__float_as_uint(f)))
#define UNPACK2(lo, hi, d) asm("mov.b64 {%0, %1}, %2;" : "=r"(lo), "=r"(hi) : "l"(d))

// ------------------------- threefry2x32 (key = [0, 42]) -------------------------
__device__ __forceinline__ uint32_t rotl32(uint32_t x, int r) { return (x << r) | (x >> (32 - r)); }
__device__ __forceinline__ void threefry2x32_42(uint32_t x0, uint32_t x1,
                                                uint32_t& o0, uint32_t& o1) {
    const uint32_t ks0 = 0u, ks1 = 42u;
    const uint32_t ks2 = 0x1BD11BDAu ^ ks0 ^ ks1;
    x0 += ks0; x1 += ks1;
#define TF_R(r) { x0 += x1; x1 = rotl32(x1, (r)); x1 ^= x0; }
    TF_R(13) TF_R(15) TF_R(26) TF_R(6)
    x0 += ks1; x1 += ks2 + 1u;
    TF_R(17) TF_R(29) TF_R(16) TF_R(24)
    x0 += ks2; x1 += ks0 + 2u;
    TF_R(13) TF_R(15) TF_R(26) TF_R(6)
    x0 += ks0; x1 += ks1 + 3u;
    TF_R(17) TF_R(29) TF_R(16) TF_R(24)
    x0 += ks1; x1 += ks2 + 4u;
    TF_R(13) TF_R(15) TF_R(26) TF_R(6)
    x0 += ks2; x1 += ks0 + 5u;
#undef TF_R
    o0 = x0; o1 = x1;
}
__device__ __forceinline__ float uniform_at(uint32_t j) {
    uint32_t r0, r1;
    threefry2x32_42(0u, j, r0, r1);
    uint32_t bits = r0 ^ r1;
    float f = __uint_as_float((bits >> 9) | 0x3f800000u) - 1.0f;
    const float TINY = 1.17549435e-38f;
    return fmaxf(TINY, f + TINY);
}
__device__ __forceinline__ float gumbel_of_u(float u) { return -logf(-logf(u)); }

// ======================= GEMM0: cz = z @ W0 + b0 (f32x2, double-buffered) =======================
__global__ void __launch_bounds__(256)
gemm0_kernel(const float* __restrict__ A, const float* __restrict__ Bm,
             const float* __restrict__ bias, float* __restrict__ C, int N, int K) {
    __shared__ float As[2][16][132];
    __shared__ float Bs[2][16][132];
    const int tid = threadIdx.x;
    const int bx = blockIdx.x, by = blockIdx.y;
    const int tx = tid & 15, ty = tid >> 4;
    const int ar = tid >> 2, ac = (tid & 3) << 2;
    const int br = tid >> 5, bc = (tid & 31) << 2;

    unsigned long long acc2[8][4];
#pragma unroll
    for (int i = 0; i < 8; i++)
#pragma unroll
        for (int j = 0; j < 4; j++) acc2[i][j] = 0ull;

    const int S = K / 16;
    float4 a4[2], b4[2];
#pragma unroll
    for (int h = 0; h < 2; h++) {
        a4[h] = *reinterpret_cast<const float4*>(&A[(size_t)(by * 128 + ar + h * 64) * K + ac]);
        b4[h] = *reinterpret_cast<const float4*>(&Bm[(size_t)(br + h * 8) * N + bx * 128 + bc]);
    }
#pragma unroll
    for (int h = 0; h < 2; h++) {
        As[0][ac + 0][ar + h * 64] = a4[h].x;
        As[0][ac + 1][ar + h * 64] = a4[h].y;
        As[0][ac + 2][ar + h * 64] = a4[h].z;
        As[0][ac + 3][ar + h * 64] = a4[h].w;
        *reinterpret_cast<float4*>(&Bs[0][br + h * 8][bc]) = b4[h];
    }
    __syncthreads();

    for (int s = 0; s < S; s++) {
        const int cur = s & 1;
        if (s + 1 < S) {
            int k1 = (s + 1) * 16;
#pragma unroll
            for (int h = 0; h < 2; h++) {
                a4[h] = *reinterpret_cast<const float4*>(&A[(size_t)(by * 128 + ar + h * 64) * K + k1 + ac]);
                b4[h] = *reinterpret_cast<const float4*>(&Bm[(size_t)(k1 + br + h * 8) * N + bx * 128 + bc]);
            }
        }
#pragma unroll
        for (int kk = 0; kk < 16; kk++) {
            float4 av0 = *reinterpret_cast<const float4*>(&As[cur][kk][ty * 8]);
            float4 av1 = *reinterpret_cast<const float4*>(&As[cur][kk][ty * 8 + 4]);
            const unsigned long long* bp =
                reinterpret_cast<const unsigned long long*>(&Bs[cur][kk][tx * 8]);
            unsigned long long b2[4];
#pragma unroll
            for (int j = 0; j < 4; j++) b2[j] = bp[j];
            unsigned long long ap[8];
            PACK2(ap[0], av0.x); PACK2(ap[1], av0.y); PACK2(ap[2], av0.z); PACK2(ap[3], av0.w);
            PACK2(ap[4], av1.x); PACK2(ap[5], av1.y); PACK2(ap[6], av1.z); PACK2(ap[7], av1.w);
#pragma unroll
            for (int i = 0; i < 8; i++)
#pragma unroll
                for (int j = 0; j < 4; j++) FFMA2(acc2[i][j], ap[i], b2[j]);
        }
        if (s + 1 < S) {
            int nb = (s + 1) & 1;
#pragma unroll
            for (int h = 0; h < 2; h++) {
                As[nb][ac + 0][ar + h * 64] = a4[h].x;
                As[nb][ac + 1][ar + h * 64] = a4[h].y;
                As[nb][ac + 2][ar + h * 64] = a4[h].z;
                As[nb][ac + 3][ar + h * 64] = a4[h].w;
                *reinterpret_cast<float4*>(&Bs[nb][br + h * 8][bc]) = b4[h];
            }
        }
        __syncthreads();
    }

#pragma unroll
    for (int i = 0; i < 8; i++) {
        int row = by * 128 + ty * 8 + i;
        int col = bx * 128 + tx * 8;
        float a[8];
#pragma unroll
        for (int j = 0; j < 4; j++) {
            uint32_t lo, hi;
            UNPACK2(lo, hi, acc2[i][j]);
            a[2 * j] = __uint_as_float(lo);
            a[2 * j + 1] = __uint_as_float(hi);
        }
#pragma unroll
        for (int j = 0; j < 8; j += 4) {
            float4 v;
            v.x = a[j + 0] + bias[col + j + 0];
            v.y = a[j + 1] + bias[col + j + 1];
            v.z = a[j + 2] + bias[col + j + 2];
            v.w = a[j + 3] + bias[col + j + 3];
            *reinterpret_cast<float4*>(&C[(size_t)row * N + col + j]) = v;
        }
    }
}

// ======================= dist: per-tile logit extrema only (no logits stored) ==================
// Per output element the accumulation is sequential FMA over k=0..255, so any logit can be
// recomputed bit-identically by a scalar fmaf loop (used in argmax for candidates).
__global__ void __launch_bounds__(256)
dist_kernel(const float* __restrict__ cz, const float* __restrict__ E,
            const float* __restrict__ czsq, const float* __restrict__ esq,
            float* __restrict__ tmax, float* __restrict__ tmin) {
    __shared__ float As[2][16][132];
    __shared__ float Bs[2][16][132];
    const int tid = threadIdx.x;
    const int bx = blockIdx.x, by = blockIdx.y;
    const int tx = tid & 15, ty = tid >> 4;
    const int ar = tid >> 2, ac = (tid & 3) << 2;

    unsigned long long acc2[8][4];
#pragma unroll
    for (int i = 0; i < 8; i++)
#pragma unroll
        for (int j = 0; j < 4; j++) acc2[i][j] = 0ull;

    const int S = kE / 16;
    float4 a4[2], b4[2];
#pragma unroll
    for (int h = 0; h < 2; h++) {
        a4[h] = *reinterpret_cast<const float4*>(&cz[(size_t)(by * 128 + ar + h * 64) * kE + ac]);
        b4[h] = *reinterpret_cast<const float4*>(&E[(size_t)(bx * 128 + ar + h * 64) * kE + ac]);
    }
#pragma unroll
    for (int h = 0; h < 2; h++) {
        As[0][ac + 0][ar + h * 64] = a4[h].x;
        As[0][ac + 1][ar + h * 64] = a4[h].y;
        As[0][ac + 2][ar + h * 64] = a4[h].z;
        As[0][ac + 3][ar + h * 64] = a4[h].w;
        Bs[0][ac + 0][ar + h * 64] = b4[h].x;
        Bs[0][ac + 1][ar + h * 64] = b4[h].y;
        Bs[0][ac + 2][ar + h * 64] = b4[h].z;
        Bs[0][ac + 3][ar + h * 64] = b4[h].w;
    }
    __syncthreads();

    for (int s = 0; s < S; s++) {
        const int cur = s & 1;
        if (s + 1 < S) {
            int k1 = (s + 1) * 16;
#pragma unroll
            for (int h = 0; h < 2; h++) {
                a4[h] = *reinterpret_cast<const float4*>(&cz[(size_t)(by * 128 + ar + h * 64) * kE + k1 + ac]);
                b4[h] = *reinterpret_cast<const float4*>(&E[(size_t)(bx * 128 + ar + h * 64) * kE + k1 + ac]);
            }
        }
#pragma unroll
        for (int kk = 0; kk < 16; kk++) {
            float4 av0 = *reinterpret_cast<const float4*>(&As[cur][kk][ty * 8]);
            float4 av1 = *reinterpret_cast<const float4*>(&As[cur][kk][ty * 8 + 4]);
            const unsigned long long* bp =
                reinterpret_cast<const unsigned long long*>(&Bs[cur][kk][tx * 8]);
            unsigned long long b2[4];
#pragma unroll
            for (int j = 0; j < 4; j++) b2[j] = bp[j];
            unsigned long long ap[8];
            PACK2(ap[0], av0.x); PACK2(ap[1], av0.y); PACK2(ap[2], av0.z); PACK2(ap[3], av0.w);
            PACK2(ap[4], av1.x); PACK2(ap[5], av1.y); PACK2(ap[6], av1.z); PACK2(ap[7], av1.w);
#pragma unroll
            for (int i = 0; i < 8; i++)
#pragma unroll
                for (int j = 0; j < 4; j++) FFMA2(acc2[i][j], ap[i], b2[j]);
        }
        if (s + 1 < S) {
            int nb = (s + 1) & 1;
#pragma unroll
            for (int h = 0; h < 2; h++) {
                As[nb][ac + 0][ar + h * 64] = a4[h].x;
                As[nb][ac + 1][ar + h * 64] = a4[h].y;
                As[nb][ac + 2][ar + h * 64] = a4[h].z;
                As[nb][ac + 3][ar + h * 64] = a4[h].w;
                Bs[nb][ac + 0][ar + h * 64] = b4[h].x;
                Bs[nb][ac + 1][ar + h * 64] = b4[h].y;
                Bs[nb][ac + 2][ar + h * 64] = b4[h].z;
                Bs[nb][ac + 3][ar + h * 64] = b4[h].w;
            }
        }
        __syncthreads();
    }

#pragma unroll
    for (int i = 0; i < 8; i++) {
        int row = by * 128 + ty * 8 + i;
        int col = bx * 128 + tx * 8;
        float cs = czsq[row];
        float a[8];
#pragma unroll
        for (int j = 0; j < 4; j++) {
            uint32_t lo, hi;
            UNPACK2(lo, hi, acc2[i][j]);
            a[2 * j] = __uint_as_float(lo);
            a[2 * j + 1] = __uint_as_float(hi);
        }
        float rmx = -INFINITY, rmn = INFINITY;
#pragma unroll
        for (int j = 0; j < 8; j++) {
            float lv = (cs + esq[col + j]) - 2.0f * a[j];
            rmx = fmaxf(rmx, lv);
            rmn = fminf(rmn, lv);
        }
        // reduce across the 16 tx lanes (xor offsets < 16 stay within half-warp)
#pragma unroll
        for (int o = 1; o < 16; o <<= 1) {
            rmx = fmaxf(rmx, __shfl_xor_sync(0xffffffffu, rmx, o));
            rmn = fminf(rmn, __shfl_xor_sync(0xffffffffu, rmn, o));
        }
        if (tx == 0) {
            tmax[(size_t)row * kNT + bx] = rmx;
            tmin[(size_t)row * kNT + bx] = rmn;
        }
    }
}

// ======================= argmax from tile extrema + candidate recompute =======================
__global__ void __launch_bounds__(128)
argmax2_kernel(const float* __restrict__ cz, const float* __restrict__ E,
               const float* __restrict__ czsq, const float* __restrict__ esq,
               const float* __restrict__ tmax, const float* __restrict__ tmin,
               int* __restrict__ outidx) {
    int row = blockIdx.x;
    int t = threadIdx.x;

    __shared__ float sCz[kE];
    __shared__ float sRed[128];
    __shared__ float sBv[128];
    __shared__ int   sBi[128];

    // stage cz row into smem (coalesced float2)
    {
        float2 v = *reinterpret_cast<const float2*>(&cz[(size_t)row * kE + t * 2]);
        sCz[t * 2] = v.x; sCz[t * 2 + 1] = v.y;
    }

    // rowmax / rowmin from tile extrema
    sRed[t] = (t < kNT) ? tmax[(size_t)row * kNT + t] : -INFINITY;
    __syncthreads();
    for (int o = 64; o > 0; o >>= 1) {
        if (t < o) sRed[t] = fmaxf(sRed[t], sRed[t + o]);
        __syncthreads();
    }
    float rowmax = sRed[0];
    __syncthreads();
    sRed[t] = (t < kNT) ? tmin[(size_t)row * kNT + t] : INFINITY;
    __syncthreads();
    for (int o = 64; o > 0; o >>= 1) {
        if (t < o) sRed[t] = fminf(sRed[t], sRed[t + o]);
        __syncthreads();
    }
    float rowmin = sRed[0];
    __syncthreads();

    // uniforms for all 2048 codes of this row; track max u
    float uu[16];
    float umax = 0.0f;
    uint32_t base = (uint32_t)row * (uint32_t)kNE;
#pragma unroll
    for (int i = 0; i < 16; i++) {
        uu[i] = uniform_at(base + (uint32_t)(i * 128 + t));
        umax = fmaxf(umax, uu[i]);
    }
    sRed[t] = umax;
    __syncthreads();
    for (int o = 64; o > 0; o >>= 1) {
        if (t < o) sRed[t] = fmaxf(sRed[t], sRed[t + o]);
        __syncthreads();
    }
    float u_top = sRed[0];
    __syncthreads();

    float D = rowmax - rowmin;
    float g_top = gumbel_of_u(u_top);
    float thr_g = g_top - D - 1e-4f;
    float u_req = expf(-expf(-thr_g)) * 0.9999f;

    float cs = czsq[row];
    float best = -INFINITY;
    int bi = kNE;
#pragma unroll
    for (int i = 0; i < 16; i++) {
        if (uu[i] >= u_req) {
            int e = i * 128 + t;
            // bit-identical recompute of the GEMM dot: sequential fmaf over k
            const float* Er = E + (size_t)e * kE;
            float acc = 0.0f;
            for (int k = 0; k < kE; k++) acc = fmaf(sCz[k], Er[k], acc);
            float lv = (cs + esq[e]) - 2.0f * acc;
            float s = (lv - rowmax) + gumbel_of_u(uu[i]);
            if (s > best || (s == best && e < bi)) { best = s; bi = e; }
        }
    }
    sBv[t] = best; sBi[t] = bi;
    __syncthreads();
    for (int o = 64; o > 0; o >>= 1) {
        if (t < o) {
            if (sBv[t + o] > sBv[t] || (sBv[t + o] == sBv[t] && sBi[t + o] < sBi[t])) {
                sBv[t] = sBv[t + o]; sBi[t] = sBi[t + o];
            }
        }
        __syncthreads();
    }
    if (t == 0) outidx[row] = sBi[0];
}

// ======================= P = E @ W1_ch =======================
__global__ void __launch_bounds__(256)
pgemm_kernel(const float* __restrict__ E, const float* __restrict__ W1,
             float* __restrict__ P) {
    __shared__ float As[2][16][132];
    __shared__ float Bs[2][16][132];
    const int tid = threadIdx.x;
    const int bx = blockIdx.x, by = blockIdx.y, ch = blockIdx.z;
    const int tx = tid & 15, ty = tid >> 4;
    const int ar = tid >> 2, ac = (tid & 3) << 2;
    const int br = tid >> 5, bc = (tid & 31) << 2;
    const float* Bm = W1 + (size_t)ch * kE * kD;

    unsigned long long acc2[8][4];
#pragma unroll
    for (int i = 0; i < 8; i++)
#pragma unroll
        for (int j = 0; j < 4; j++) acc2[i][j] = 0ull;

    const int S = kE / 16;
    float4 a4[2], b4[2];
#pragma unroll
    for (int h = 0; h < 2; h++) {
        a4[h] = *reinterpret_cast<const float4*>(&E[(size_t)(by * 128 + ar + h * 64) * kE + ac]);
        b4[h] = *reinterpret_cast<const float4*>(&Bm[(size_t)(br + h * 8) * kD + bx * 128 + bc]);
    }
#pragma unroll
    for (int h = 0; h < 2; h++) {
        As[0][ac + 0][ar + h * 64] = a4[h].x;
        As[0][ac + 1][ar + h * 64] = a4[h].y;
        As[0][ac + 2][ar + h * 64] = a4[h].z;
        As[0][ac + 3][ar + h * 64] = a4[h].w;
        *reinterpret_cast<float4*>(&Bs[0][br + h * 8][bc]) = b4[h];
    }
    __syncthreads();

    for (int s = 0; s < S; s++) {
        const int cur = s & 1;
        if (s + 1 < S) {
            int k1 = (s + 1) * 16;
#pragma unroll
            for (int h = 0; h < 2; h++) {
                a4[h] = *reinterpret_cast<const float4*>(&E[(size_t)(by * 128 + ar + h * 64) * kE + k1 + ac]);
                b4[h] = *reinterpret_cast<const float4*>(&Bm[(size_t)(k1 + br + h * 8) * kD + bx * 128 + bc]);
            }
        }
#pragma unroll
        for (int kk = 0; kk < 16; kk++) {
            float4 av0 = *reinterpret_cast<const float4*>(&As[cur][kk][ty * 8]);
            float4 av1 = *reinterpret_cast<const float4*>(&As[cur][kk][ty * 8 + 4]);
            const unsigned long long* bp =
                reinterpret_cast<const unsigned long long*>(&Bs[cur][kk][tx * 8]);
            unsigned long long b2[4];
#pragma unroll
            for (int j = 0; j < 4; j++) b2[j] = bp[j];
            unsigned long long ap[8];
            PACK2(ap[0], av0.x); PACK2(ap[1], av0.y); PACK2(ap[2], av0.z); PACK2(ap[3], av0.w);
            PACK2(ap[4], av1.x); PACK2(ap[5], av1.y); PACK2(ap[6], av1.z); PACK2(ap[7], av1.w);
#pragma unroll
            for (int i = 0; i < 8; i++)
#pragma unroll
                for (int j = 0; j < 4; j++) FFMA2(acc2[i][j], ap[i], b2[j]);
        }
        if (s + 1 < S) {
            int nb = (s + 1) & 1;
#pragma unroll
            for (int h = 0; h < 2; h++) {
                As[nb][ac + 0][ar + h * 64] = a4[h].x;
                As[nb][ac + 1][ar + h * 64] = a4[h].y;
                As[nb][ac + 2][ar + h * 64] = a4[h].z;
                As[nb][ac + 3][ar + h * 64] = a4[h].w;
                *reinterpret_cast<float4*>(&Bs[nb][br + h * 8][bc]) = b4[h];
            }
        }
        __syncthreads();
    }

    float* Pout = P + (size_t)ch * kNE * kD;
#pragma unroll
    for (int i = 0; i < 8; i++) {
        int row = by * 128 + ty * 8 + i;
        int col = bx * 128 + tx * 8;
#pragma unroll
        for (int j = 0; j < 4; j++) {
            uint32_t lo, hi;
            UNPACK2(lo, hi, acc2[i][j]);
            float2 v;
            v.x = __uint_as_float(lo);
            v.y = __uint_as_float(hi);
            *reinterpret_cast<float2*>(&Pout[(size_t)row * kD + col + 2 * j]) = v;
        }
    }
}

// ======================= z_q gather =======================
__global__ void __launch_bounds__(256)
gather_zq_kernel(const float* __restrict__ P, const int* __restrict__ idx,
                 const float* __restrict__ b1, float* __restrict__ out) {
    int m = blockIdx.x;
    int c = threadIdx.x * 4;
    int4 id = *reinterpret_cast<const int4*>(&idx[m * 4]);
    float4 p0 = *reinterpret_cast<const float4*>(&P[((size_t)0 * kNE + id.x) * kD + c]);
    float4 p1 = *reinterpret_cast<const float4*>(&P[((size_t)1 * kNE + id.y) * kD + c]);
    float4 p2 = *reinterpret_cast<const float4*>(&P[((size_t)2 * kNE + id.z) * kD + c]);
    float4 p3 = *reinterpret_cast<const float4*>(&P[((size_t)3 * kNE + id.w) * kD + c]);
    float4 bb = *reinterpret_cast<const float4*>(&b1[c]);
    float4 v;
    v.x = ((p0.x + p1.x) + p2.x) + p3.x + bb.x;
    v.y = ((p0.y + p1.y) + p2.y) + p3.y + bb.y;
    v.z = ((p0.z + p1.z) + p2.z) + p3.z + bb.z;
    v.w = ((p0.w + p1.w) + p2.w) + p3.w + bb.w;
    size_t o = (size_t)m * kD + c;
    out[o + 0] = v.x; out[o + 1] = v.y; out[o + 2] = v.z; out[o + 3] = v.w;
}

// ------------------------- row squared norms -------------------------
__global__ void rowsq_kernel(const float* __restrict__ X, float* __restrict__ out, int ncols4) {
    int row = blockIdx.x * 8 + (threadIdx.x >> 5);
    int lane = threadIdx.x & 31;
    const float4* p = reinterpret_cast<const float4*>(X + (size_t)row * (ncols4 * 4));
    double s = 0.0;
    for (int i = lane; i < ncols4; i += 32) {
        float4 v = p[i];
        s += (double)v.x * v.x + (double)v.y * v.y + (double)v.z * v.z + (double)v.w * v.w;
    }
#pragma unroll
    for (int o = 16; o > 0; o >>= 1) s += __shfl_xor_sync(0xffffffffu, s, o);
    if (lane == 0) out[row] = (float)s;
}

// ------------------------- loss -------------------------
__global__ void __launch_bounds__(256)
loss_kernel(const float* __restrict__ cz, const int* __restrict__ idx,
            const float* __restrict__ E, double* __restrict__ part) {
    double s = 0.0;
    size_t blockBase = (size_t)blockIdx.x * 4096;
#pragma unroll
    for (int i = 0; i < 16; i++) {
        size_t g = blockBase + (size_t)i * 256 + threadIdx.x;
        int rowr = (int)(g >> 8);
        int pos = (int)(g & 255);
        float d = E[(size_t)idx[rowr] * kE + pos] - cz[g];
        s += (double)d * d;
    }
    __shared__ double sd[256];
    sd[threadIdx.x] = s;
    __syncthreads();
    for (int o = 128; o > 0; o >>= 1) {
        if (threadIdx.x < o) sd[threadIdx.x] += sd[threadIdx.x + o];
        __syncthreads();
    }
    if (threadIdx.x == 0) part[blockIdx.x] = sd[0];
}

__global__ void loss_final_kernel(const double* __restrict__ part, float* __restrict__ out) {
    double s = 0.0;
    for (int i = threadIdx.x; i < 4096; i += 256) s += part[i];
    __shared__ double sd[256];
    sd[threadIdx.x] = s;
    __syncthreads();
    for (int o = 128; o > 0; o >>= 1) {
        if (threadIdx.x < o) sd[threadIdx.x] += sd[threadIdx.x + o];
        __syncthreads();
    }
    if (threadIdx.x == 0) {
        float m = (float)(sd[0] / 16777216.0);
        out[0] = m + 0.25f * m;
    }
}

// ------------------------- launch (serial, default stream) -------------------------
extern "C" void kernel_launch(void* const* d_in, const int* in_sizes, int n_in,
                              void* d_out, int out_size) {
    const float* z  = (const float*)d_in[0];
    const float* W0 = (const float*)d_in[1];
    const float* b0 = (const float*)d_in[2];
    const float* W1 = (const float*)d_in[3];
    const float* b1 = (const float*)d_in[4];
    const float* E  = (const float*)d_in[5];
    float* out = (float*)d_out;

    float *p_cz, *p_esq, *p_czsq, *p_P, *p_tmax, *p_tmin;
    int* p_idx;
    double* p_part;
    cudaGetSymbolAddress((void**)&p_cz, g_cz);
    cudaGetSymbolAddress((void**)&p_esq, g_esq);
    cudaGetSymbolAddress((void**)&p_czsq, g_czsq);
    cudaGetSymbolAddress((void**)&p_idx, g_idx);
    cudaGetSymbolAddress((void**)&p_part, g_part);
    cudaGetSymbolAddress((void**)&p_P, g_P);
    cudaGetSymbolAddress((void**)&p_tmax, g_tmax);
    cudaGetSymbolAddress((void**)&p_tmin, g_tmin);

    // P = E @ W1 per channel (idx-independent)
    pgemm_kernel<<<dim3(kD / 128, kNE / 128, kCH), 256>>>(E, W1, p_P);
    // cz = z @ W0 + b0
    gemm0_kernel<<<dim3(kD / 128, kM1 / 128), 256>>>(z, W0, b0, p_cz, kD, kD);
    // row squared norms
    rowsq_kernel<<<kNE / 8, 256>>>(E, p_esq, kE / 4);
    rowsq_kernel<<<kMR / 8, 256>>>(p_cz, p_czsq, kE / 4);
    // distance tile extrema (no logits materialized)
    dist_kernel<<<dim3(kNE / 128, kMR / 128), 256>>>(p_cz, E, p_czsq, p_esq, p_tmax, p_tmin);
    // categorical sample: prune + bit-identical candidate recompute
    argmax2_kernel<<<kMR, 128>>>(p_cz, E, p_czsq, p_esq, p_tmax, p_tmin, p_idx);

    int zoff = out_size - kM1 * kD;
    if (zoff >= 1) {
        loss_kernel<<<4096, 256>>>(p_cz, p_idx, E, p_part);
        loss_final_kernel<<<1, 256>>>(p_part, out);
    }
    if (out_size >= kM1 * kD) {
        float* zq = out + (zoff > 0 ? zoff : 0);
        gather_zq_kernel<<<kM1, 256>>>(p_P, p_idx, b1, zq);
    }
}

// round 8
// speedup vs baseline: 1.7781x; 1.7781x over previous
#include <cuda_runtime.h>
#include <cstdint>
#include <math.h>

// Problem constants
#define kD    1024
#define kE    256
#define kNE   2048
#define kCH   4
#define kM1   16384
#define kMR   65536

// -------- scratch (static device globals; no allocations) --------
__device__ float  g_cz[(size_t)kM1 * kD];          // 64 MB
__device__ float  g_P[(size_t)kCH * kNE * kD];     // 32 MB
__device__ float  g_esq[kNE];
__device__ float  g_esq_mm[2];                     // [max, min]
__device__ float  g_czsq[kMR];
__device__ int    g_idx[kMR];
__device__ double g_part[4096];

// ------------------------- f32x2 packed FMA helpers -------------------------
#define FFMA2(d, a, b) asm("fma.rn.f32x2 %0, %1, %2, %0;" : "+l"(d) : "l"(a), "l"(b))
#define PACK2(d, f)    asm("mov.b64 %0, {%1, %1};" : "=l"(d) : "r"(__float_as_uint(f)))
#define UNPACK2(lo, hi, d) asm("mov.b64 {%0, %1}, %2;" : "=r"(lo), "=r"(hi) : "l"(d))

// ------------------------- threefry2x32 (key = [0, 42]) -------------------------
__device__ __forceinline__ uint32_t rotl32(uint32_t x, int r) { return (x << r) | (x >> (32 - r)); }
__device__ __forceinline__ void threefry2x32_42(uint32_t x0, uint32_t x1,
                                                uint32_t& o0, uint32_t& o1) {
    const uint32_t ks0 = 0u, ks1 = 42u;
    const uint32_t ks2 = 0x1BD11BDAu ^ ks0 ^ ks1;
    x0 += ks0; x1 += ks1;
#define TF_R(r) { x0 += x1; x1 = rotl32(x1, (r)); x1 ^= x0; }
    TF_R(13) TF_R(15) TF_R(26) TF_R(6)
    x0 += ks1; x1 += ks2 + 1u;
    TF_R(17) TF_R(29) TF_R(16) TF_R(24)
    x0 += ks2; x1 += ks0 + 2u;
    TF_R(13) TF_R(15) TF_R(26) TF_R(6)
    x0 += ks0; x1 += ks1 + 3u;
    TF_R(17) TF_R(29) TF_R(16) TF_R(24)
    x0 += ks1; x1 += ks2 + 4u;
    TF_R(13) TF_R(15) TF_R(26) TF_R(6)
    x0 += ks2; x1 += ks0 + 5u;
#undef TF_R
    o0 = x0; o1 = x1;
}
__device__ __forceinline__ float uniform_at(uint32_t j) {
    uint32_t r0, r1;
    threefry2x32_42(0u, j, r0, r1);
    uint32_t bits = r0 ^ r1;
    float f = __uint_as_float((bits >> 9) | 0x3f800000u) - 1.0f;
    const float TINY = 1.17549435e-38f;
    return fmaxf(TINY, f + TINY);
}
__device__ __forceinline__ float gumbel_of_u(float u) { return -logf(-logf(u)); }

// ======================= GEMM0: cz = z @ W0 + b0 (f32x2, double-buffered) =======================
__global__ void __launch_bounds__(256)
gemm0_kernel(const float* __restrict__ A, const float* __restrict__ Bm,
             const float* __restrict__ bias, float* __restrict__ C, int N, int K) {
    __shared__ float As[2][16][132];
    __shared__ float Bs[2][16][132];
    const int tid = threadIdx.x;
    const int bx = blockIdx.x, by = blockIdx.y;
    const int tx = tid & 15, ty = tid >> 4;
    const int ar = tid >> 2, ac = (tid & 3) << 2;
    const int br = tid >> 5, bc = (tid & 31) << 2;

    unsigned long long acc2[8][4];
#pragma unroll
    for (int i = 0; i < 8; i++)
#pragma unroll
        for (int j = 0; j < 4; j++) acc2[i][j] = 0ull;

    const int S = K / 16;
    float4 a4[2], b4[2];
#pragma unroll
    for (int h = 0; h < 2; h++) {
        a4[h] = *reinterpret_cast<const float4*>(&A[(size_t)(by * 128 + ar + h * 64) * K + ac]);
        b4[h] = *reinterpret_cast<const float4*>(&Bm[(size_t)(br + h * 8) * N + bx * 128 + bc]);
    }
#pragma unroll
    for (int h = 0; h < 2; h++) {
        As[0][ac + 0][ar + h * 64] = a4[h].x;
        As[0][ac + 1][ar + h * 64] = a4[h].y;
        As[0][ac + 2][ar + h * 64] = a4[h].z;
        As[0][ac + 3][ar + h * 64] = a4[h].w;
        *reinterpret_cast<float4*>(&Bs[0][br + h * 8][bc]) = b4[h];
    }
    __syncthreads();

    for (int s = 0; s < S; s++) {
        const int cur = s & 1;
        if (s + 1 < S) {
            int k1 = (s + 1) * 16;
#pragma unroll
            for (int h = 0; h < 2; h++) {
                a4[h] = *reinterpret_cast<const float4*>(&A[(size_t)(by * 128 + ar + h * 64) * K + k1 + ac]);
                b4[h] = *reinterpret_cast<const float4*>(&Bm[(size_t)(k1 + br + h * 8) * N + bx * 128 + bc]);
            }
        }
#pragma unroll
        for (int kk = 0; kk < 16; kk++) {
            float4 av0 = *reinterpret_cast<const float4*>(&As[cur][kk][ty * 8]);
            float4 av1 = *reinterpret_cast<const float4*>(&As[cur][kk][ty * 8 + 4]);
            const unsigned long long* bp =
                reinterpret_cast<const unsigned long long*>(&Bs[cur][kk][tx * 8]);
            unsigned long long b2[4];
#pragma unroll
            for (int j = 0; j < 4; j++) b2[j] = bp[j];
            unsigned long long ap[8];
            PACK2(ap[0], av0.x); PACK2(ap[1], av0.y); PACK2(ap[2], av0.z); PACK2(ap[3], av0.w);
            PACK2(ap[4], av1.x); PACK2(ap[5], av1.y); PACK2(ap[6], av1.z); PACK2(ap[7], av1.w);
#pragma unroll
            for (int i = 0; i < 8; i++)
#pragma unroll
                for (int j = 0; j < 4; j++) FFMA2(acc2[i][j], ap[i], b2[j]);
        }
        if (s + 1 < S) {
            int nb = (s + 1) & 1;
#pragma unroll
            for (int h = 0; h < 2; h++) {
                As[nb][ac + 0][ar + h * 64] = a4[h].x;
                As[nb][ac + 1][ar + h * 64] = a4[h].y;
                As[nb][ac + 2][ar + h * 64] = a4[h].z;
                As[nb][ac + 3][ar + h * 64] = a4[h].w;
                *reinterpret_cast<float4*>(&Bs[nb][br + h * 8][bc]) = b4[h];
            }
        }
        __syncthreads();
    }

#pragma unroll
    for (int i = 0; i < 8; i++) {
        int row = by * 128 + ty * 8 + i;
        int col = bx * 128 + tx * 8;
        float a[8];
#pragma unroll
        for (int j = 0; j < 4; j++) {
            uint32_t lo, hi;
            UNPACK2(lo, hi, acc2[i][j]);
            a[2 * j] = __uint_as_float(lo);
            a[2 * j + 1] = __uint_as_float(hi);
        }
#pragma unroll
        for (int j = 0; j < 8; j += 4) {
            float4 v;
            v.x = a[j + 0] + bias[col + j + 0];
            v.y = a[j + 1] + bias[col + j + 1];
            v.z = a[j + 2] + bias[col + j + 2];
            v.w = a[j + 3] + bias[col + j + 3];
            *reinterpret_cast<float4*>(&C[(size_t)row * N + col + j]) = v;
        }
    }
}

// ======================= P = E @ W1_ch =======================
__global__ void __launch_bounds__(256)
pgemm_kernel(const float* __restrict__ E, const float* __restrict__ W1,
             float* __restrict__ P) {
    __shared__ float As[2][16][132];
    __shared__ float Bs[2][16][132];
    const int tid = threadIdx.x;
    const int bx = blockIdx.x, by = blockIdx.y, ch = blockIdx.z;
    const int tx = tid & 15, ty = tid >> 4;
    const int ar = tid >> 2, ac = (tid & 3) << 2;
    const int br = tid >> 5, bc = (tid & 31) << 2;
    const float* Bm = W1 + (size_t)ch * kE * kD;

    unsigned long long acc2[8][4];
#pragma unroll
    for (int i = 0; i < 8; i++)
#pragma unroll
        for (int j = 0; j < 4; j++) acc2[i][j] = 0ull;

    const int S = kE / 16;
    float4 a4[2], b4[2];
#pragma unroll
    for (int h = 0; h < 2; h++) {
        a4[h] = *reinterpret_cast<const float4*>(&E[(size_t)(by * 128 + ar + h * 64) * kE + ac]);
        b4[h] = *reinterpret_cast<const float4*>(&Bm[(size_t)(br + h * 8) * kD + bx * 128 + bc]);
    }
#pragma unroll
    for (int h = 0; h < 2; h++) {
        As[0][ac + 0][ar + h * 64] = a4[h].x;
        As[0][ac + 1][ar + h * 64] = a4[h].y;
        As[0][ac + 2][ar + h * 64] = a4[h].z;
        As[0][ac + 3][ar + h * 64] = a4[h].w;
        *reinterpret_cast<float4*>(&Bs[0][br + h * 8][bc]) = b4[h];
    }
    __syncthreads();

    for (int s = 0; s < S; s++) {
        const int cur = s & 1;
        if (s + 1 < S) {
            int k1 = (s + 1) * 16;
#pragma unroll
            for (int h = 0; h < 2; h++) {
                a4[h] = *reinterpret_cast<const float4*>(&E[(size_t)(by * 128 + ar + h * 64) * kE + k1 + ac]);
                b4[h] = *reinterpret_cast<const float4*>(&Bm[(size_t)(k1 + br + h * 8) * kD + bx * 128 + bc]);
            }
        }
#pragma unroll
        for (int kk = 0; kk < 16; kk++) {
            float4 av0 = *reinterpret_cast<const float4*>(&As[cur][kk][ty * 8]);
            float4 av1 = *reinterpret_cast<const float4*>(&As[cur][kk][ty * 8 + 4]);
            const unsigned long long* bp =
                reinterpret_cast<const unsigned long long*>(&Bs[cur][kk][tx * 8]);
            unsigned long long b2[4];
#pragma unroll
            for (int j = 0; j < 4; j++) b2[j] = bp[j];
            unsigned long long ap[8];
            PACK2(ap[0], av0.x); PACK2(ap[1], av0.y); PACK2(ap[2], av0.z); PACK2(ap[3], av0.w);
            PACK2(ap[4], av1.x); PACK2(ap[5], av1.y); PACK2(ap[6], av1.z); PACK2(ap[7], av1.w);
#pragma unroll
            for (int i = 0; i < 8; i++)
#pragma unroll
                for (int j = 0; j < 4; j++) FFMA2(acc2[i][j], ap[i], b2[j]);
        }
        if (s + 1 < S) {
            int nb = (s + 1) & 1;
#pragma unroll
            for (int h = 0; h < 2; h++) {
                As[nb][ac + 0][ar + h * 64] = a4[h].x;
                As[nb][ac + 1][ar + h * 64] = a4[h].y;
                As[nb][ac + 2][ar + h * 64] = a4[h].z;
                As[nb][ac + 3][ar + h * 64] = a4[h].w;
                *reinterpret_cast<float4*>(&Bs[nb][br + h * 8][bc]) = b4[h];
            }
        }
        __syncthreads();
    }

    float* Pout = P + (size_t)ch * kNE * kD;
#pragma unroll
    for (int i = 0; i < 8; i++) {
        int row = by * 128 + ty * 8 + i;
        int col = bx * 128 + tx * 8;
#pragma unroll
        for (int j = 0; j < 4; j++) {
            uint32_t lo, hi;
            UNPACK2(lo, hi, acc2[i][j]);
            float2 v;
            v.x = __uint_as_float(lo);
            v.y = __uint_as_float(hi);
            *reinterpret_cast<float2*>(&Pout[(size_t)row * kD + col + 2 * j]) = v;
        }
    }
}

// ======================= row squared norms (4 rows per warp, double accumulate) ================
// Double accumulation is order-insensitive at this precision (rounds to the exact fp32 sum),
// so restructuring for MLP does not change czsq bits.
__global__ void __launch_bounds__(256)
rowsq4_kernel(const float* __restrict__ X, float* __restrict__ out) {
    int warp = threadIdx.x >> 5, lane = threadIdx.x & 31;
    int row0 = blockIdx.x * 32 + warp * 4;
    float4 va[4][2];
#pragma unroll
    for (int r = 0; r < 4; r++) {
        const float4* p = reinterpret_cast<const float4*>(X + (size_t)(row0 + r) * kE);
        va[r][0] = p[lane];
        va[r][1] = p[lane + 32];
    }
    double s[4];
#pragma unroll
    for (int r = 0; r < 4; r++) {
        double s0 = (double)va[r][0].x * va[r][0].x + (double)va[r][0].y * va[r][0].y;
        double s1 = (double)va[r][0].z * va[r][0].z + (double)va[r][0].w * va[r][0].w;
        double s2 = (double)va[r][1].x * va[r][1].x + (double)va[r][1].y * va[r][1].y;
        double s3 = (double)va[r][1].z * va[r][1].z + (double)va[r][1].w * va[r][1].w;
        s[r] = (s0 + s1) + (s2 + s3);
    }
#pragma unroll
    for (int o = 16; o > 0; o >>= 1) {
#pragma unroll
        for (int r = 0; r < 4; r++) s[r] += __shfl_xor_sync(0xffffffffu, s[r], o);
    }
    if (lane < 4) out[row0 + lane] = (float)s[lane];
}

// esq max/min (single block)
__global__ void __launch_bounds__(256)
esq_minmax_kernel(const float* __restrict__ esq, float* __restrict__ mm) {
    int t = threadIdx.x;
    float mx = -INFINITY, mn = INFINITY;
    for (int i = t; i < kNE; i += 256) {
        float v = esq[i];
        mx = fmaxf(mx, v);
        mn = fminf(mn, v);
    }
    __shared__ float sMx[256], sMn[256];
    sMx[t] = mx; sMn[t] = mn;
    __syncthreads();
    for (int o = 128; o > 0; o >>= 1) {
        if (t < o) {
            sMx[t] = fmaxf(sMx[t], sMx[t + o]);
            sMn[t] = fminf(sMn[t], sMn[t + o]);
        }
        __syncthreads();
    }
    if (t == 0) { mm[0] = sMx[0]; mm[1] = sMn[0]; }
}

// ======================= argmax: analytic prune + candidate-only exact logits ==================
// D_bound >= rowmax - rowmin analytically:
//   lv_e = fl(fl(cs + esq_e) - 2 dot_e),  |2 dot_e| <= 2 ||cz|| ||e||
//   spread <= 4 sqrt(cs) sqrt(esq_max) + (esq_max - esq_min) + pads.
// Candidates with g < g_top - D_bound provably cannot win; only they get the 256-FMA dot
// (sequential fmaf over k — same rounding order as the FFMA2 GEMM that passed in R4).
__global__ void __launch_bounds__(128)
argmax3_kernel(const float* __restrict__ cz, const float* __restrict__ E,
               const float* __restrict__ czsq, const float* __restrict__ esq,
               const float* __restrict__ esq_mm, int* __restrict__ outidx) {
    int row = blockIdx.x;
    int t = threadIdx.x;

    __shared__ float sCz[kE];
    __shared__ float sRed[128];
    __shared__ float sBv[128];
    __shared__ int   sBi[128];

    {
        float2 v = *reinterpret_cast<const float2*>(&cz[(size_t)row * kE + t * 2]);
        sCz[t * 2] = v.x; sCz[t * 2 + 1] = v.y;
    }
    float cs = czsq[row];
    float emax = esq_mm[0], emin = esq_mm[1];

    // uniforms for all 2048 codes of this row; find max u
    float uu[16];
    float umax = 0.0f;
    uint32_t base = (uint32_t)row * (uint32_t)kNE;
#pragma unroll
    for (int i = 0; i < 16; i++) {
        uu[i] = uniform_at(base + (uint32_t)(i * 128 + t));
        umax = fmaxf(umax, uu[i]);
    }
    sRed[t] = umax;
    __syncthreads();
    for (int o = 64; o > 0; o >>= 1) {
        if (t < o) sRed[t] = fmaxf(sRed[t], sRed[t + o]);
        __syncthreads();
    }
    float u_top = sRed[0];
    __syncthreads();

    // analytic logit-spread bound (generous fp pads)
    float D = 4.04f * sqrtf(cs) * sqrtf(emax) + (emax - emin) + 1e-3f;
    float g_top = gumbel_of_u(u_top);
    float thr_g = g_top - D - 1e-4f;
    float u_req = expf(-expf(-thr_g)) * 0.9999f;

    float best = -INFINITY;
    int bi = kNE;
#pragma unroll
    for (int i = 0; i < 16; i++) {
        if (uu[i] >= u_req) {
            int e = i * 128 + t;
            const float* Er = E + (size_t)e * kE;
            float acc = 0.0f;
#pragma unroll 16
            for (int k = 0; k < kE; k++) acc = fmaf(sCz[k], Er[k], acc);
            float lv = (cs + esq[e]) - 2.0f * acc;
            // Sterbenz-exact shift by cs (common to all candidates in the row)
            float s = (lv - cs) + gumbel_of_u(uu[i]);
            if (s > best || (s == best && e < bi)) { best = s; bi = e; }
        }
    }
    sBv[t] = best; sBi[t] = bi;
    __syncthreads();
    for (int o = 64; o > 0; o >>= 1) {
        if (t < o) {
            if (sBv[t + o] > sBv[t] || (sBv[t + o] == sBv[t] && sBi[t + o] < sBi[t])) {
                sBv[t] = sBv[t + o]; sBi[t] = sBi[t + o];
            }
        }
        __syncthreads();
    }
    if (t == 0) outidx[row] = sBi[0];
}

// ======================= z_q gather =======================
__global__ void __launch_bounds__(256)
gather_zq_kernel(const float* __restrict__ P, const int* __restrict__ idx,
                 const float* __restrict__ b1, float* __restrict__ out) {
    int m = blockIdx.x;
    int c = threadIdx.x * 4;
    int4 id = *reinterpret_cast<const int4*>(&idx[m * 4]);
    float4 p0 = *reinterpret_cast<const float4*>(&P[((size_t)0 * kNE + id.x) * kD + c]);
    float4 p1 = *reinterpret_cast<const float4*>(&P[((size_t)1 * kNE + id.y) * kD + c]);
    float4 p2 = *reinterpret_cast<const float4*>(&P[((size_t)2 * kNE + id.z) * kD + c]);
    float4 p3 = *reinterpret_cast<const float4*>(&P[((size_t)3 * kNE + id.w) * kD + c]);
    float4 bb = *reinterpret_cast<const float4*>(&b1[c]);
    float4 v;
    v.x = ((p0.x + p1.x) + p2.x) + p3.x + bb.x;
    v.y = ((p0.y + p1.y) + p2.y) + p3.y + bb.y;
    v.z = ((p0.z + p1.z) + p2.z) + p3.z + bb.z;
    v.w = ((p0.w + p1.w) + p2.w) + p3.w + bb.w;
    size_t o = (size_t)m * kD + c;
    out[o + 0] = v.x; out[o + 1] = v.y; out[o + 2] = v.z; out[o + 3] = v.w;
}

// ------------------------- loss -------------------------
__global__ void __launch_bounds__(256)
loss_kernel(const float* __restrict__ cz, const int* __restrict__ idx,
            const float* __restrict__ E, double* __restrict__ part) {
    double s = 0.0;
    size_t blockBase = (size_t)blockIdx.x * 4096;
#pragma unroll
    for (int i = 0; i < 16; i++) {
        size_t g = blockBase + (size_t)i * 256 + threadIdx.x;
        int rowr = (int)(g >> 8);
        int pos = (int)(g & 255);
        float d = E[(size_t)idx[rowr] * kE + pos] - cz[g];
        s += (double)d * d;
    }
    __shared__ double sd[256];
    sd[threadIdx.x] = s;
    __syncthreads();
    for (int o = 128; o > 0; o >>= 1) {
        if (threadIdx.x < o) sd[threadIdx.x] += sd[threadIdx.x + o];
        __syncthreads();
    }
    if (threadIdx.x == 0) part[blockIdx.x] = sd[0];
}

__global__ void loss_final_kernel(const double* __restrict__ part, float* __restrict__ out) {
    double s = 0.0;
    for (int i = threadIdx.x; i < 4096; i += 256) s += part[i];
    __shared__ double sd[256];
    sd[threadIdx.x] = s;
    __syncthreads();
    for (int o = 128; o > 0; o >>= 1) {
        if (threadIdx.x < o) sd[threadIdx.x] += sd[threadIdx.x + o];
        __syncthreads();
    }
    if (threadIdx.x == 0) {
        float m = (float)(sd[0] / 16777216.0);
        out[0] = m + 0.25f * m;
    }
}

// ------------------------- launch (serial, default stream) -------------------------
extern "C" void kernel_launch(void* const* d_in, const int* in_sizes, int n_in,
                              void* d_out, int out_size) {
    const float* z  = (const float*)d_in[0];
    const float* W0 = (const float*)d_in[1];
    const float* b0 = (const float*)d_in[2];
    const float* W1 = (const float*)d_in[3];
    const float* b1 = (const float*)d_in[4];
    const float* E  = (const float*)d_in[5];
    float* out = (float*)d_out;

    float *p_cz, *p_esq, *p_esq_mm, *p_czsq, *p_P;
    int* p_idx;
    double* p_part;
    cudaGetSymbolAddress((void**)&p_cz, g_cz);
    cudaGetSymbolAddress((void**)&p_esq, g_esq);
    cudaGetSymbolAddress((void**)&p_esq_mm, g_esq_mm);
    cudaGetSymbolAddress((void**)&p_czsq, g_czsq);
    cudaGetSymbolAddress((void**)&p_idx, g_idx);
    cudaGetSymbolAddress((void**)&p_part, g_part);
    cudaGetSymbolAddress((void**)&p_P, g_P);

    // P = E @ W1 per channel (idx-independent)
    pgemm_kernel<<<dim3(kD / 128, kNE / 128, kCH), 256>>>(E, W1, p_P);
    // cz = z @ W0 + b0
    gemm0_kernel<<<dim3(kD / 128, kM1 / 128), 256>>>(z, W0, b0, p_cz, kD, kD);
    // row squared norms + esq extrema
    rowsq4_kernel<<<kNE / 32, 256>>>(E, p_esq);
    esq_minmax_kernel<<<1, 256>>>(p_esq, p_esq_mm);
    rowsq4_kernel<<<kMR / 32, 256>>>(p_cz, p_czsq);
    // categorical sample: analytic prune + candidate-only exact logits (no dist GEMM!)
    argmax3_kernel<<<kMR, 128>>>(p_cz, E, p_czsq, p_esq, p_esq_mm, p_idx);

    int zoff = out_size - kM1 * kD;
    if (zoff >= 1) {
        loss_kernel<<<4096, 256>>>(p_cz, p_idx, E, p_part);
        loss_final_kernel<<<1, 256>>>(p_part, out);
    }
    if (out_size >= kM1 * kD) {
        float* zq = out + (zoff > 0 ? zoff : 0);
        gather_zq_kernel<<<kM1, 256>>>(p_P, p_idx, b1, zq);
    }
}

// round 9
// speedup vs baseline: 1.8000x; 1.0123x over previous
#include <cuda_runtime.h>
#include <cstdint>
#include <math.h>

// Problem constants
#define kD    1024
#define kE    256
#define kNE   2048
#define kCH   4
#define kM1   16384
#define kMR   65536
#define NCHUNK 4
#define M1C   (kM1 / NCHUNK)   // 4096 gemm0 rows per chunk
#define MRC   (kMR / NCHUNK)   // 16384 code rows per chunk

// -------- scratch (static device globals; no allocations) --------
__device__ float  g_cz[(size_t)kM1 * kD];          // 64 MB
__device__ float  g_P[(size_t)kCH * kNE * kD];     // 32 MB
__device__ float  g_esq[kNE];
__device__ float  g_esq_mm[2];                     // [max, min]
__device__ float  g_czsq[kMR];
__device__ float  g_lv[kMR];                       // winner squared distance per row
__device__ int    g_idx[kMR];

// ------------------------- f32x2 packed FMA helpers -------------------------
#define FFMA2(d, a, b) asm("fma.rn.f32x2 %0, %1, %2, %0;" : "+l"(d) : "l"(a), "l"(b))
#define PACK2(d, f)    asm("mov.b64 %0, {%1, %1};" : "=l"(d) : "r"(__float_as_uint(f)))
#define UNPACK2(lo, hi, d) asm("mov.b64 {%0, %1}, %2;" : "=r"(lo), "=r"(hi) : "l"(d))

// ------------------------- threefry2x32 (key = [0, 42]) -------------------------
__device__ __forceinline__ uint32_t rotl32(uint32_t x, int r) { return (x << r) | (x >> (32 - r)); }
__device__ __forceinline__ void threefry2x32_42(uint32_t x0, uint32_t x1,
                                                uint32_t& o0, uint32_t& o1) {
    const uint32_t ks0 = 0u, ks1 = 42u;
    const uint32_t ks2 = 0x1BD11BDAu ^ ks0 ^ ks1;
    x0 += ks0; x1 += ks1;
#define TF_R(r) { x0 += x1; x1 = rotl32(x1, (r)); x1 ^= x0; }
    TF_R(13) TF_R(15) TF_R(26) TF_R(6)
    x0 += ks1; x1 += ks2 + 1u;
    TF_R(17) TF_R(29) TF_R(16) TF_R(24)
    x0 += ks2; x1 += ks0 + 2u;
    TF_R(13) TF_R(15) TF_R(26) TF_R(6)
    x0 += ks0; x1 += ks1 + 3u;
    TF_R(17) TF_R(29) TF_R(16) TF_R(24)
    x0 += ks1; x1 += ks2 + 4u;
    TF_R(13) TF_R(15) TF_R(26) TF_R(6)
    x0 += ks2; x1 += ks0 + 5u;
#undef TF_R
    o0 = x0; o1 = x1;
}
__device__ __forceinline__ float uniform_at(uint32_t j) {
    uint32_t r0, r1;
    threefry2x32_42(0u, j, r0, r1);
    uint32_t bits = r0 ^ r1;
    float f = __uint_as_float((bits >> 9) | 0x3f800000u) - 1.0f;
    const float TINY = 1.17549435e-38f;
    return fmaxf(TINY, f + TINY);
}
__device__ __forceinline__ float gumbel_of_u(float u) { return -logf(-logf(u)); }

// ======================= GEMM0: cz = z @ W0 + b0 (f32x2, double-buffered) =======================
__global__ void __launch_bounds__(256)
gemm0_kernel(const float* __restrict__ A, const float* __restrict__ Bm,
             const float* __restrict__ bias, float* __restrict__ C, int N, int K) {
    __shared__ float As[2][16][132];
    __shared__ float Bs[2][16][132];
    const int tid = threadIdx.x;
    const int bx = blockIdx.x, by = blockIdx.y;
    const int tx = tid & 15, ty = tid >> 4;
    const int ar = tid >> 2, ac = (tid & 3) << 2;
    const int br = tid >> 5, bc = (tid & 31) << 2;

    unsigned long long acc2[8][4];
#pragma unroll
    for (int i = 0; i < 8; i++)
#pragma unroll
        for (int j = 0; j < 4; j++) acc2[i][j] = 0ull;

    const int S = K / 16;
    float4 a4[2], b4[2];
#pragma unroll
    for (int h = 0; h < 2; h++) {
        a4[h] = *reinterpret_cast<const float4*>(&A[(size_t)(by * 128 + ar + h * 64) * K + ac]);
        b4[h] = *reinterpret_cast<const float4*>(&Bm[(size_t)(br + h * 8) * N + bx * 128 + bc]);
    }
#pragma unroll
    for (int h = 0; h < 2; h++) {
        As[0][ac + 0][ar + h * 64] = a4[h].x;
        As[0][ac + 1][ar + h * 64] = a4[h].y;
        As[0][ac + 2][ar + h * 64] = a4[h].z;
        As[0][ac + 3][ar + h * 64] = a4[h].w;
        *reinterpret_cast<float4*>(&Bs[0][br + h * 8][bc]) = b4[h];
    }
    __syncthreads();

    for (int s = 0; s < S; s++) {
        const int cur = s & 1;
        if (s + 1 < S) {
            int k1 = (s + 1) * 16;
#pragma unroll
            for (int h = 0; h < 2; h++) {
                a4[h] = *reinterpret_cast<const float4*>(&A[(size_t)(by * 128 + ar + h * 64) * K + k1 + ac]);
                b4[h] = *reinterpret_cast<const float4*>(&Bm[(size_t)(k1 + br + h * 8) * N + bx * 128 + bc]);
            }
        }
#pragma unroll
        for (int kk = 0; kk < 16; kk++) {
            float4 av0 = *reinterpret_cast<const float4*>(&As[cur][kk][ty * 8]);
            float4 av1 = *reinterpret_cast<const float4*>(&As[cur][kk][ty * 8 + 4]);
            const unsigned long long* bp =
                reinterpret_cast<const unsigned long long*>(&Bs[cur][kk][tx * 8]);
            unsigned long long b2[4];
#pragma unroll
            for (int j = 0; j < 4; j++) b2[j] = bp[j];
            unsigned long long ap[8];
            PACK2(ap[0], av0.x); PACK2(ap[1], av0.y); PACK2(ap[2], av0.z); PACK2(ap[3], av0.w);
            PACK2(ap[4], av1.x); PACK2(ap[5], av1.y); PACK2(ap[6], av1.z); PACK2(ap[7], av1.w);
#pragma unroll
            for (int i = 0; i < 8; i++)
#pragma unroll
                for (int j = 0; j < 4; j++) FFMA2(acc2[i][j], ap[i], b2[j]);
        }
        if (s + 1 < S) {
            int nb = (s + 1) & 1;
#pragma unroll
            for (int h = 0; h < 2; h++) {
                As[nb][ac + 0][ar + h * 64] = a4[h].x;
                As[nb][ac + 1][ar + h * 64] = a4[h].y;
                As[nb][ac + 2][ar + h * 64] = a4[h].z;
                As[nb][ac + 3][ar + h * 64] = a4[h].w;
                *reinterpret_cast<float4*>(&Bs[nb][br + h * 8][bc]) = b4[h];
            }
        }
        __syncthreads();
    }

#pragma unroll
    for (int i = 0; i < 8; i++) {
        int row = by * 128 + ty * 8 + i;
        int col = bx * 128 + tx * 8;
        float a[8];
#pragma unroll
        for (int j = 0; j < 4; j++) {
            uint32_t lo, hi;
            UNPACK2(lo, hi, acc2[i][j]);
            a[2 * j] = __uint_as_float(lo);
            a[2 * j + 1] = __uint_as_float(hi);
        }
#pragma unroll
        for (int j = 0; j < 8; j += 4) {
            float4 v;
            v.x = a[j + 0] + bias[col + j + 0];
            v.y = a[j + 1] + bias[col + j + 1];
            v.z = a[j + 2] + bias[col + j + 2];
            v.w = a[j + 3] + bias[col + j + 3];
            *reinterpret_cast<float4*>(&C[(size_t)row * N + col + j]) = v;
        }
    }
}

// ======================= P = E @ W1_ch =======================
__global__ void __launch_bounds__(256)
pgemm_kernel(const float* __restrict__ E, const float* __restrict__ W1,
             float* __restrict__ P) {
    __shared__ float As[2][16][132];
    __shared__ float Bs[2][16][132];
    const int tid = threadIdx.x;
    const int bx = blockIdx.x, by = blockIdx.y, ch = blockIdx.z;
    const int tx = tid & 15, ty = tid >> 4;
    const int ar = tid >> 2, ac = (tid & 3) << 2;
    const int br = tid >> 5, bc = (tid & 31) << 2;
    const float* Bm = W1 + (size_t)ch * kE * kD;

    unsigned long long acc2[8][4];
#pragma unroll
    for (int i = 0; i < 8; i++)
#pragma unroll
        for (int j = 0; j < 4; j++) acc2[i][j] = 0ull;

    const int S = kE / 16;
    float4 a4[2], b4[2];
#pragma unroll
    for (int h = 0; h < 2; h++) {
        a4[h] = *reinterpret_cast<const float4*>(&E[(size_t)(by * 128 + ar + h * 64) * kE + ac]);
        b4[h] = *reinterpret_cast<const float4*>(&Bm[(size_t)(br + h * 8) * kD + bx * 128 + bc]);
    }
#pragma unroll
    for (int h = 0; h < 2; h++) {
        As[0][ac + 0][ar + h * 64] = a4[h].x;
        As[0][ac + 1][ar + h * 64] = a4[h].y;
        As[0][ac + 2][ar + h * 64] = a4[h].z;
        As[0][ac + 3][ar + h * 64] = a4[h].w;
        *reinterpret_cast<float4*>(&Bs[0][br + h * 8][bc]) = b4[h];
    }
    __syncthreads();

    for (int s = 0; s < S; s++) {
        const int cur = s & 1;
        if (s + 1 < S) {
            int k1 = (s + 1) * 16;
#pragma unroll
            for (int h = 0; h < 2; h++) {
                a4[h] = *reinterpret_cast<const float4*>(&E[(size_t)(by * 128 + ar + h * 64) * kE + k1 + ac]);
                b4[h] = *reinterpret_cast<const float4*>(&Bm[(size_t)(k1 + br + h * 8) * kD + bx * 128 + bc]);
            }
        }
#pragma unroll
        for (int kk = 0; kk < 16; kk++) {
            float4 av0 = *reinterpret_cast<const float4*>(&As[cur][kk][ty * 8]);
            float4 av1 = *reinterpret_cast<const float4*>(&As[cur][kk][ty * 8 + 4]);
            const unsigned long long* bp =
                reinterpret_cast<const unsigned long long*>(&Bs[cur][kk][tx * 8]);
            unsigned long long b2[4];
#pragma unroll
            for (int j = 0; j < 4; j++) b2[j] = bp[j];
            unsigned long long ap[8];
            PACK2(ap[0], av0.x); PACK2(ap[1], av0.y); PACK2(ap[2], av0.z); PACK2(ap[3], av0.w);
            PACK2(ap[4], av1.x); PACK2(ap[5], av1.y); PACK2(ap[6], av1.z); PACK2(ap[7], av1.w);
#pragma unroll
            for (int i = 0; i < 8; i++)
#pragma unroll
                for (int j = 0; j < 4; j++) FFMA2(acc2[i][j], ap[i], b2[j]);
        }
        if (s + 1 < S) {
            int nb = (s + 1) & 1;
#pragma unroll
            for (int h = 0; h < 2; h++) {
                As[nb][ac + 0][ar + h * 64] = a4[h].x;
                As[nb][ac + 1][ar + h * 64] = a4[h].y;
                As[nb][ac + 2][ar + h * 64] = a4[h].z;
                As[nb][ac + 3][ar + h * 64] = a4[h].w;
                *reinterpret_cast<float4*>(&Bs[nb][br + h * 8][bc]) = b4[h];
            }
        }
        __syncthreads();
    }

    float* Pout = P + (size_t)ch * kNE * kD;
#pragma unroll
    for (int i = 0; i < 8; i++) {
        int row = by * 128 + ty * 8 + i;
        int col = bx * 128 + tx * 8;
#pragma unroll
        for (int j = 0; j < 4; j++) {
            uint32_t lo, hi;
            UNPACK2(lo, hi, acc2[i][j]);
            float2 v;
            v.x = __uint_as_float(lo);
            v.y = __uint_as_float(hi);
            *reinterpret_cast<float2*>(&Pout[(size_t)row * kD + col + 2 * j]) = v;
        }
    }
}

// ======================= row squared norms (4 rows per warp, double accumulate) ================
__global__ void __launch_bounds__(256)
rowsq4_kernel(const float* __restrict__ X, float* __restrict__ out) {
    int warp = threadIdx.x >> 5, lane = threadIdx.x & 31;
    int row0 = blockIdx.x * 32 + warp * 4;
    float4 va[4][2];
#pragma unroll
    for (int r = 0; r < 4; r++) {
        const float4* p = reinterpret_cast<const float4*>(X + (size_t)(row0 + r) * kE);
        va[r][0] = p[lane];
        va[r][1] = p[lane + 32];
    }
    double s[4];
#pragma unroll
    for (int r = 0; r < 4; r++) {
        double s0 = (double)va[r][0].x * va[r][0].x + (double)va[r][0].y * va[r][0].y;
        double s1 = (double)va[r][0].z * va[r][0].z + (double)va[r][0].w * va[r][0].w;
        double s2 = (double)va[r][1].x * va[r][1].x + (double)va[r][1].y * va[r][1].y;
        double s3 = (double)va[r][1].z * va[r][1].z + (double)va[r][1].w * va[r][1].w;
        s[r] = (s0 + s1) + (s2 + s3);
    }
#pragma unroll
    for (int o = 16; o > 0; o >>= 1) {
#pragma unroll
        for (int r = 0; r < 4; r++) s[r] += __shfl_xor_sync(0xffffffffu, s[r], o);
    }
    if (lane < 4) out[row0 + lane] = (float)s[lane];
}

// esq max/min (single block)
__global__ void __launch_bounds__(256)
esq_minmax_kernel(const float* __restrict__ esq, float* __restrict__ mm) {
    int t = threadIdx.x;
    float mx = -INFINITY, mn = INFINITY;
    for (int i = t; i < kNE; i += 256) {
        float v = esq[i];
        mx = fmaxf(mx, v);
        mn = fminf(mn, v);
    }
    __shared__ float sMx[256], sMn[256];
    sMx[t] = mx; sMn[t] = mn;
    __syncthreads();
    for (int o = 128; o > 0; o >>= 1) {
        if (t < o) {
            sMx[t] = fmaxf(sMx[t], sMx[t + o]);
            sMn[t] = fminf(sMn[t], sMn[t + o]);
        }
        __syncthreads();
    }
    if (t == 0) { mm[0] = sMx[0]; mm[1] = sMn[0]; }
}

// ======================= argmax: analytic prune + candidate-only exact logits ==================
// Also emits the winner's lv (its exact squared distance) for the fused loss.
__global__ void __launch_bounds__(128)
argmax3_kernel(const float* __restrict__ cz, const float* __restrict__ E,
               const float* __restrict__ czsq, const float* __restrict__ esq,
               const float* __restrict__ esq_mm, int* __restrict__ outidx,
               float* __restrict__ outlv, int rowBase) {
    int row = blockIdx.x;
    int t = threadIdx.x;

    __shared__ float sCz[kE];
    __shared__ float sRed[128];
    __shared__ float sBv[128];
    __shared__ float sLv[128];
    __shared__ int   sBi[128];

    {
        float2 v = *reinterpret_cast<const float2*>(&cz[(size_t)row * kE + t * 2]);
        sCz[t * 2] = v.x; sCz[t * 2 + 1] = v.y;
    }
    float cs = czsq[row];
    float emax = esq_mm[0], emin = esq_mm[1];

    // uniforms for all 2048 codes of this row; find max u
    float uu[16];
    float umax = 0.0f;
    uint32_t base = (uint32_t)(rowBase + row) * (uint32_t)kNE;
#pragma unroll
    for (int i = 0; i < 16; i++) {
        uu[i] = uniform_at(base + (uint32_t)(i * 128 + t));
        umax = fmaxf(umax, uu[i]);
    }
    sRed[t] = umax;
    __syncthreads();
    for (int o = 64; o > 0; o >>= 1) {
        if (t < o) sRed[t] = fmaxf(sRed[t], sRed[t + o]);
        __syncthreads();
    }
    float u_top = sRed[0];
    __syncthreads();

    // analytic logit-spread bound (generous fp pads)
    float D = 4.04f * sqrtf(cs) * sqrtf(emax) + (emax - emin) + 1e-3f;
    float g_top = gumbel_of_u(u_top);
    float thr_g = g_top - D - 1e-4f;
    float u_req = expf(-expf(-thr_g)) * 0.9999f;

    float best = -INFINITY, bestlv = 0.0f;
    int bi = kNE;
#pragma unroll
    for (int i = 0; i < 16; i++) {
        if (uu[i] >= u_req) {
            int e = i * 128 + t;
            const float* Er = E + (size_t)e * kE;
            float acc = 0.0f;
#pragma unroll 16
            for (int k = 0; k < kE; k++) acc = fmaf(sCz[k], Er[k], acc);
            float lv = (cs + esq[e]) - 2.0f * acc;
            float s = (lv - cs) + gumbel_of_u(uu[i]);
            if (s > best || (s == best && e < bi)) { best = s; bi = e; bestlv = lv; }
        }
    }
    sBv[t] = best; sBi[t] = bi; sLv[t] = bestlv;
    __syncthreads();
    for (int o = 64; o > 0; o >>= 1) {
        if (t < o) {
            if (sBv[t + o] > sBv[t] || (sBv[t + o] == sBv[t] && sBi[t + o] < sBi[t])) {
                sBv[t] = sBv[t + o]; sBi[t] = sBi[t + o]; sLv[t] = sLv[t + o];
            }
        }
        __syncthreads();
    }
    if (t == 0) { outidx[row] = sBi[0]; outlv[row] = sLv[0]; }
}

// ======================= z_q gather =======================
__global__ void __launch_bounds__(256)
gather_zq_kernel(const float* __restrict__ P, const int* __restrict__ idx,
                 const float* __restrict__ b1, float* __restrict__ out) {
    int m = blockIdx.x;
    int c = threadIdx.x * 4;
    int4 id = *reinterpret_cast<const int4*>(&idx[m * 4]);
    float4 p0 = *reinterpret_cast<const float4*>(&P[((size_t)0 * kNE + id.x) * kD + c]);
    float4 p1 = *reinterpret_cast<const float4*>(&P[((size_t)1 * kNE + id.y) * kD + c]);
    float4 p2 = *reinterpret_cast<const float4*>(&P[((size_t)2 * kNE + id.z) * kD + c]);
    float4 p3 = *reinterpret_cast<const float4*>(&P[((size_t)3 * kNE + id.w) * kD + c]);
    float4 bb = *reinterpret_cast<const float4*>(&b1[c]);
    float4 v;
    v.x = ((p0.x + p1.x) + p2.x) + p3.x + bb.x;
    v.y = ((p0.y + p1.y) + p2.y) + p3.y + bb.y;
    v.z = ((p0.z + p1.z) + p2.z) + p3.z + bb.z;
    v.w = ((p0.w + p1.w) + p2.w) + p3.w + bb.w;
    size_t o = (size_t)m * kD + c;
    out[o + 0] = v.x; out[o + 1] = v.y; out[o + 2] = v.z; out[o + 3] = v.w;
}

// ------------------------- loss from winner lv: out[0] = 1.25 * sum(lv) / 2^24 -----------------
__global__ void __launch_bounds__(1024)
lvsum_kernel(const float* __restrict__ lv, float* __restrict__ out) {
    int t = threadIdx.x;
    double s = 0.0;
    for (int i = t; i < kMR; i += 1024) s += (double)lv[i];
    __shared__ double sd[1024];
    sd[t] = s;
    __syncthreads();
    for (int o = 512; o > 0; o >>= 1) {
        if (t < o) sd[t] += sd[t + o];
        __syncthreads();
    }
    if (t == 0) {
        float m = (float)(sd[0] / 16777216.0);
        out[0] = m + 0.25f * m;
    }
}

// ------------------------- launch (chunked gemm0 || argmax pipeline) -------------------------
extern "C" void kernel_launch(void* const* d_in, const int* in_sizes, int n_in,
                              void* d_out, int out_size) {
    const float* z  = (const float*)d_in[0];
    const float* W0 = (const float*)d_in[1];
    const float* b0 = (const float*)d_in[2];
    const float* W1 = (const float*)d_in[3];
    const float* b1 = (const float*)d_in[4];
    const float* E  = (const float*)d_in[5];
    float* out = (float*)d_out;

    float *p_cz, *p_esq, *p_esq_mm, *p_czsq, *p_P, *p_lv;
    int* p_idx;
    cudaGetSymbolAddress((void**)&p_cz, g_cz);
    cudaGetSymbolAddress((void**)&p_esq, g_esq);
    cudaGetSymbolAddress((void**)&p_esq_mm, g_esq_mm);
    cudaGetSymbolAddress((void**)&p_czsq, g_czsq);
    cudaGetSymbolAddress((void**)&p_idx, g_idx);
    cudaGetSymbolAddress((void**)&p_P, g_P);
    cudaGetSymbolAddress((void**)&p_lv, g_lv);

    static cudaStream_t sB = 0;
    static cudaEvent_t evFork, evEnd, evA[NCHUNK];
    static bool init_done = false;
    if (!init_done) {
        if (cudaStreamCreateWithFlags(&sB, cudaStreamNonBlocking) != cudaSuccess) sB = 0;
        cudaEventCreateWithFlags(&evFork, cudaEventDisableTiming);
        cudaEventCreateWithFlags(&evEnd, cudaEventDisableTiming);
        for (int c = 0; c < NCHUNK; c++)
            cudaEventCreateWithFlags(&evA[c], cudaEventDisableTiming);
        init_done = true;
    }

    int zoff = out_size - kM1 * kD;
    float* zq = out + (zoff > 0 ? zoff : 0);
    bool do_loss = (zoff >= 1);
    bool do_zq = (out_size >= kM1 * kD);

    // fork sB from the capture stream
    cudaEventRecord(evFork, 0);
    cudaStreamWaitEvent(sB, evFork, 0);

    // sB: codebook-side precomputes (independent of cz)
    pgemm_kernel<<<dim3(kD / 128, kNE / 128, kCH), 256, 0, sB>>>(E, W1, p_P);
    rowsq4_kernel<<<kNE / 32, 256, 0, sB>>>(E, p_esq);
    esq_minmax_kernel<<<1, 256, 0, sB>>>(p_esq, p_esq_mm);

    // stream0: gemm0 chunks; sB consumes each chunk (rowsq -> argmax -> gather)
    for (int c = 0; c < NCHUNK; c++) {
        gemm0_kernel<<<dim3(kD / 128, M1C / 128), 256>>>(
            z + (size_t)c * M1C * kD, W0, b0, p_cz + (size_t)c * M1C * kD, kD, kD);
        cudaEventRecord(evA[c], 0);
        cudaStreamWaitEvent(sB, evA[c], 0);
        rowsq4_kernel<<<MRC / 32, 256, 0, sB>>>(p_cz + (size_t)c * M1C * kD,
                                                p_czsq + (size_t)c * MRC);
        argmax3_kernel<<<MRC, 128, 0, sB>>>(p_cz + (size_t)c * M1C * kD, E,
                                            p_czsq + (size_t)c * MRC, p_esq, p_esq_mm,
                                            p_idx + (size_t)c * MRC,
                                            p_lv + (size_t)c * MRC, c * MRC);
        if (do_zq)
            gather_zq_kernel<<<M1C, 256, 0, sB>>>(p_P, p_idx + (size_t)c * MRC, b1,
                                                  zq + (size_t)c * M1C * kD);
    }
    if (do_loss)
        lvsum_kernel<<<1, 1024, 0, sB>>>(p_lv, out);

    // join sB back into the capture stream
    cudaEventRecord(evEnd, sB);
    cudaStreamWaitEvent(0, evEnd, 0);
}

// round 10
// speedup vs baseline: 2.0070x; 1.1150x over previous
#include <cuda_runtime.h>
#include <cstdint>
#include <math.h>

// Problem constants
#define kD    1024
#define kE    256
#define kNE   2048
#define kCH   4
#define kM1   16384
#define kMR   65536
#define NCHUNK 4
#define M1C   (kM1 / NCHUNK)   // 4096 gemm0 rows per chunk
#define MRC   (kMR / NCHUNK)   // 16384 code rows per chunk

// -------- scratch (static device globals; no allocations) --------
__device__ float  g_cz[(size_t)kM1 * kD];          // 64 MB
__device__ float  g_P[(size_t)kCH * kNE * kD];     // 32 MB
__device__ float  g_esq[kNE];
__device__ float  g_esq_mm[2];                     // [max, min]
__device__ float  g_czsq[kMR];
__device__ float  g_lv[kMR];                       // winner squared distance per row
__device__ int    g_idx[kMR];

// ------------------------- f32x2 packed FMA helpers -------------------------
#define FFMA2(d, a, b) asm("fma.rn.f32x2 %0, %1, %2, %0;" : "+l"(d) : "l"(a), "l"(b))
#define PACK2(d, f)    asm("mov.b64 %0, {%1, %1};" : "=l"(d) : "r"(__float_as_uint(f)))
#define UNPACK2(lo, hi, d) asm("mov.b64 {%0, %1}, %2;" : "=r"(lo), "=r"(hi) : "l"(d))

// ------------------------- threefry2x32 (key = [0, 42]) -------------------------
__device__ __forceinline__ uint32_t rotl32(uint32_t x, int r) { return (x << r) | (x >> (32 - r)); }
__device__ __forceinline__ void threefry2x32_42(uint32_t x0, uint32_t x1,
                                                uint32_t& o0, uint32_t& o1) {
    const uint32_t ks0 = 0u, ks1 = 42u;
    const uint32_t ks2 = 0x1BD11BDAu ^ ks0 ^ ks1;
    x0 += ks0; x1 += ks1;
#define TF_R(r) { x0 += x1; x1 = rotl32(x1, (r)); x1 ^= x0; }
    TF_R(13) TF_R(15) TF_R(26) TF_R(6)
    x0 += ks1; x1 += ks2 + 1u;
    TF_R(17) TF_R(29) TF_R(16) TF_R(24)
    x0 += ks2; x1 += ks0 + 2u;
    TF_R(13) TF_R(15) TF_R(26) TF_R(6)
    x0 += ks0; x1 += ks1 + 3u;
    TF_R(17) TF_R(29) TF_R(16) TF_R(24)
    x0 += ks1; x1 += ks2 + 4u;
    TF_R(13) TF_R(15) TF_R(26) TF_R(6)
    x0 += ks2; x1 += ks0 + 5u;
#undef TF_R
    o0 = x0; o1 = x1;
}
__device__ __forceinline__ float uniform_at(uint32_t j) {
    uint32_t r0, r1;
    threefry2x32_42(0u, j, r0, r1);
    uint32_t bits = r0 ^ r1;
    float f = __uint_as_float((bits >> 9) | 0x3f800000u) - 1.0f;
    const float TINY = 1.17549435e-38f;
    return fmaxf(TINY, f + TINY);
}
__device__ __forceinline__ float gumbel_of_u(float u) { return -logf(-logf(u)); }

// ======================= GEMM0: cz = z @ W0 + b0 (f32x2, double-buffered, 2 CTA/SM) ============
__global__ void __launch_bounds__(256, 2)
gemm0_kernel(const float* __restrict__ A, const float* __restrict__ Bm,
             const float* __restrict__ bias, float* __restrict__ C, int N, int K) {
    __shared__ float As[2][16][132];
    __shared__ float Bs[2][16][132];
    const int tid = threadIdx.x;
    const int bx = blockIdx.x, by = blockIdx.y;
    const int tx = tid & 15, ty = tid >> 4;
    const int ar = tid >> 2, ac = (tid & 3) << 2;
    const int br = tid >> 5, bc = (tid & 31) << 2;

    unsigned long long acc2[8][4];
#pragma unroll
    for (int i = 0; i < 8; i++)
#pragma unroll
        for (int j = 0; j < 4; j++) acc2[i][j] = 0ull;

    const int S = K / 16;
    float4 a4[2], b4[2];
#pragma unroll
    for (int h = 0; h < 2; h++) {
        a4[h] = *reinterpret_cast<const float4*>(&A[(size_t)(by * 128 + ar + h * 64) * K + ac]);
        b4[h] = *reinterpret_cast<const float4*>(&Bm[(size_t)(br + h * 8) * N + bx * 128 + bc]);
    }
#pragma unroll
    for (int h = 0; h < 2; h++) {
        As[0][ac + 0][ar + h * 64] = a4[h].x;
        As[0][ac + 1][ar + h * 64] = a4[h].y;
        As[0][ac + 2][ar + h * 64] = a4[h].z;
        As[0][ac + 3][ar + h * 64] = a4[h].w;
        *reinterpret_cast<float4*>(&Bs[0][br + h * 8][bc]) = b4[h];
    }
    __syncthreads();

    for (int s = 0; s < S; s++) {
        const int cur = s & 1;
        if (s + 1 < S) {
            int k1 = (s + 1) * 16;
#pragma unroll
            for (int h = 0; h < 2; h++) {
                a4[h] = *reinterpret_cast<const float4*>(&A[(size_t)(by * 128 + ar + h * 64) * K + k1 + ac]);
                b4[h] = *reinterpret_cast<const float4*>(&Bm[(size_t)(k1 + br + h * 8) * N + bx * 128 + bc]);
            }
        }
#pragma unroll
        for (int kk = 0; kk < 16; kk++) {
            float4 av0 = *reinterpret_cast<const float4*>(&As[cur][kk][ty * 8]);
            float4 av1 = *reinterpret_cast<const float4*>(&As[cur][kk][ty * 8 + 4]);
            const unsigned long long* bp =
                reinterpret_cast<const unsigned long long*>(&Bs[cur][kk][tx * 8]);
            unsigned long long b2[4];
#pragma unroll
            for (int j = 0; j < 4; j++) b2[j] = bp[j];
            unsigned long long ap[8];
            PACK2(ap[0], av0.x); PACK2(ap[1], av0.y); PACK2(ap[2], av0.z); PACK2(ap[3], av0.w);
            PACK2(ap[4], av1.x); PACK2(ap[5], av1.y); PACK2(ap[6], av1.z); PACK2(ap[7], av1.w);
#pragma unroll
            for (int i = 0; i < 8; i++)
#pragma unroll
                for (int j = 0; j < 4; j++) FFMA2(acc2[i][j], ap[i], b2[j]);
        }
        if (s + 1 < S) {
            int nb = (s + 1) & 1;
#pragma unroll
            for (int h = 0; h < 2; h++) {
                As[nb][ac + 0][ar + h * 64] = a4[h].x;
                As[nb][ac + 1][ar + h * 64] = a4[h].y;
                As[nb][ac + 2][ar + h * 64] = a4[h].z;
                As[nb][ac + 3][ar + h * 64] = a4[h].w;
                *reinterpret_cast<float4*>(&Bs[nb][br + h * 8][bc]) = b4[h];
            }
        }
        __syncthreads();
    }

#pragma unroll
    for (int i = 0; i < 8; i++) {
        int row = by * 128 + ty * 8 + i;
        int col = bx * 128 + tx * 8;
        float a[8];
#pragma unroll
        for (int j = 0; j < 4; j++) {
            uint32_t lo, hi;
            UNPACK2(lo, hi, acc2[i][j]);
            a[2 * j] = __uint_as_float(lo);
            a[2 * j + 1] = __uint_as_float(hi);
        }
#pragma unroll
        for (int j = 0; j < 8; j += 4) {
            float4 v;
            v.x = a[j + 0] + bias[col + j + 0];
            v.y = a[j + 1] + bias[col + j + 1];
            v.z = a[j + 2] + bias[col + j + 2];
            v.w = a[j + 3] + bias[col + j + 3];
            *reinterpret_cast<float4*>(&C[(size_t)row * N + col + j]) = v;
        }
    }
}

// ======================= P = E @ W1_ch (2 CTA/SM) =======================
__global__ void __launch_bounds__(256, 2)
pgemm_kernel(const float* __restrict__ E, const float* __restrict__ W1,
             float* __restrict__ P) {
    __shared__ float As[2][16][132];
    __shared__ float Bs[2][16][132];
    const int tid = threadIdx.x;
    const int bx = blockIdx.x, by = blockIdx.y, ch = blockIdx.z;
    const int tx = tid & 15, ty = tid >> 4;
    const int ar = tid >> 2, ac = (tid & 3) << 2;
    const int br = tid >> 5, bc = (tid & 31) << 2;
    const float* Bm = W1 + (size_t)ch * kE * kD;

    unsigned long long acc2[8][4];
#pragma unroll
    for (int i = 0; i < 8; i++)
#pragma unroll
        for (int j = 0; j < 4; j++) acc2[i][j] = 0ull;

    const int S = kE / 16;
    float4 a4[2], b4[2];
#pragma unroll
    for (int h = 0; h < 2; h++) {
        a4[h] = *reinterpret_cast<const float4*>(&E[(size_t)(by * 128 + ar + h * 64) * kE + ac]);
        b4[h] = *reinterpret_cast<const float4*>(&Bm[(size_t)(br + h * 8) * kD + bx * 128 + bc]);
    }
#pragma unroll
    for (int h = 0; h < 2; h++) {
        As[0][ac + 0][ar + h * 64] = a4[h].x;
        As[0][ac + 1][ar + h * 64] = a4[h].y;
        As[0][ac + 2][ar + h * 64] = a4[h].z;
        As[0][ac + 3][ar + h * 64] = a4[h].w;
        *reinterpret_cast<float4*>(&Bs[0][br + h * 8][bc]) = b4[h];
    }
    __syncthreads();

    for (int s = 0; s < S; s++) {
        const int cur = s & 1;
        if (s + 1 < S) {
            int k1 = (s + 1) * 16;
#pragma unroll
            for (int h = 0; h < 2; h++) {
                a4[h] = *reinterpret_cast<const float4*>(&E[(size_t)(by * 128 + ar + h * 64) * kE + k1 + ac]);
                b4[h] = *reinterpret_cast<const float4*>(&Bm[(size_t)(k1 + br + h * 8) * kD + bx * 128 + bc]);
            }
        }
#pragma unroll
        for (int kk = 0; kk < 16; kk++) {
            float4 av0 = *reinterpret_cast<const float4*>(&As[cur][kk][ty * 8]);
            float4 av1 = *reinterpret_cast<const float4*>(&As[cur][kk][ty * 8 + 4]);
            const unsigned long long* bp =
                reinterpret_cast<const unsigned long long*>(&Bs[cur][kk][tx * 8]);
            unsigned long long b2[4];
#pragma unroll
            for (int j = 0; j < 4; j++) b2[j] = bp[j];
            unsigned long long ap[8];
            PACK2(ap[0], av0.x); PACK2(ap[1], av0.y); PACK2(ap[2], av0.z); PACK2(ap[3], av0.w);
            PACK2(ap[4], av1.x); PACK2(ap[5], av1.y); PACK2(ap[6], av1.z); PACK2(ap[7], av1.w);
#pragma unroll
            for (int i = 0; i < 8; i++)
#pragma unroll
                for (int j = 0; j < 4; j++) FFMA2(acc2[i][j], ap[i], b2[j]);
        }
        if (s + 1 < S) {
            int nb = (s + 1) & 1;
#pragma unroll
            for (int h = 0; h < 2; h++) {
                As[nb][ac + 0][ar + h * 64] = a4[h].x;
                As[nb][ac + 1][ar + h * 64] = a4[h].y;
                As[nb][ac + 2][ar + h * 64] = a4[h].z;
                As[nb][ac + 3][ar + h * 64] = a4[h].w;
                *reinterpret_cast<float4*>(&Bs[nb][br + h * 8][bc]) = b4[h];
            }
        }
        __syncthreads();
    }

    float* Pout = P + (size_t)ch * kNE * kD;
#pragma unroll
    for (int i = 0; i < 8; i++) {
        int row = by * 128 + ty * 8 + i;
        int col = bx * 128 + tx * 8;
#pragma unroll
        for (int j = 0; j < 4; j++) {
            uint32_t lo, hi;
            UNPACK2(lo, hi, acc2[i][j]);
            float2 v;
            v.x = __uint_as_float(lo);
            v.y = __uint_as_float(hi);
            *reinterpret_cast<float2*>(&Pout[(size_t)row * kD + col + 2 * j]) = v;
        }
    }
}

// ======================= row squared norms (4 rows per warp, double accumulate) ================
__global__ void __launch_bounds__(256)
rowsq4_kernel(const float* __restrict__ X, float* __restrict__ out) {
    int warp = threadIdx.x >> 5, lane = threadIdx.x & 31;
    int row0 = blockIdx.x * 32 + warp * 4;
    float4 va[4][2];
#pragma unroll
    for (int r = 0; r < 4; r++) {
        const float4* p = reinterpret_cast<const float4*>(X + (size_t)(row0 + r) * kE);
        va[r][0] = p[lane];
        va[r][1] = p[lane + 32];
    }
    double s[4];
#pragma unroll
    for (int r = 0; r < 4; r++) {
        double s0 = (double)va[r][0].x * va[r][0].x + (double)va[r][0].y * va[r][0].y;
        double s1 = (double)va[r][0].z * va[r][0].z + (double)va[r][0].w * va[r][0].w;
        double s2 = (double)va[r][1].x * va[r][1].x + (double)va[r][1].y * va[r][1].y;
        double s3 = (double)va[r][1].z * va[r][1].z + (double)va[r][1].w * va[r][1].w;
        s[r] = (s0 + s1) + (s2 + s3);
    }
#pragma unroll
    for (int o = 16; o > 0; o >>= 1) {
#pragma unroll
        for (int r = 0; r < 4; r++) s[r] += __shfl_xor_sync(0xffffffffu, s[r], o);
    }
    if (lane < 4) out[row0 + lane] = (float)s[lane];
}

// esq max/min (single block)
__global__ void __launch_bounds__(256)
esq_minmax_kernel(const float* __restrict__ esq, float* __restrict__ mm) {
    int t = threadIdx.x;
    float mx = -INFINITY, mn = INFINITY;
    for (int i = t; i < kNE; i += 256) {
        float v = esq[i];
        mx = fmaxf(mx, v);
        mn = fminf(mn, v);
    }
    __shared__ float sMx[256], sMn[256];
    sMx[t] = mx; sMn[t] = mn;
    __syncthreads();
    for (int o = 128; o > 0; o >>= 1) {
        if (t < o) {
            sMx[t] = fmaxf(sMx[t], sMx[t + o]);
            sMn[t] = fminf(sMn[t], sMn[t + o]);
        }
        __syncthreads();
    }
    if (t == 0) { mm[0] = sMx[0]; mm[1] = sMn[0]; }
}

// ======================= argmax: analytic prune + candidate-only exact logits ==================
__global__ void __launch_bounds__(128)
argmax3_kernel(const float* __restrict__ cz, const float* __restrict__ E,
               const float* __restrict__ czsq, const float* __restrict__ esq,
               const float* __restrict__ esq_mm, int* __restrict__ outidx,
               float* __restrict__ outlv, int rowBase) {
    int row = blockIdx.x;
    int t = threadIdx.x;

    __shared__ float sCz[kE];
    __shared__ float sRed[128];
    __shared__ float sBv[128];
    __shared__ float sLv[128];
    __shared__ int   sBi[128];

    {
        float2 v = *reinterpret_cast<const float2*>(&cz[(size_t)row * kE + t * 2]);
        sCz[t * 2] = v.x; sCz[t * 2 + 1] = v.y;
    }
    float cs = czsq[row];
    float emax = esq_mm[0], emin = esq_mm[1];

    float uu[16];
    float umax = 0.0f;
    uint32_t base = (uint32_t)(rowBase + row) * (uint32_t)kNE;
#pragma unroll
    for (int i = 0; i < 16; i++) {
        uu[i] = uniform_at(base + (uint32_t)(i * 128 + t));
        umax = fmaxf(umax, uu[i]);
    }
    sRed[t] = umax;
    __syncthreads();
    for (int o = 64; o > 0; o >>= 1) {
        if (t < o) sRed[t] = fmaxf(sRed[t], sRed[t + o]);
        __syncthreads();
    }
    float u_top = sRed[0];
    __syncthreads();

    float D = 4.04f * sqrtf(cs) * sqrtf(emax) + (emax - emin) + 1e-3f;
    float g_top = gumbel_of_u(u_top);
    float thr_g = g_top - D - 1e-4f;
    float u_req = expf(-expf(-thr_g)) * 0.9999f;

    float best = -INFINITY, bestlv = 0.0f;
    int bi = kNE;
#pragma unroll
    for (int i = 0; i < 16; i++) {
        if (uu[i] >= u_req) {
            int e = i * 128 + t;
            const float* Er = E + (size_t)e * kE;
            float acc = 0.0f;
#pragma unroll 16
            for (int k = 0; k < kE; k++) acc = fmaf(sCz[k], Er[k], acc);
            float lv = (cs + esq[e]) - 2.0f * acc;
            float s = (lv - cs) + gumbel_of_u(uu[i]);
            if (s > best || (s == best && e < bi)) { best = s; bi = e; bestlv = lv; }
        }
    }
    sBv[t] = best; sBi[t] = bi; sLv[t] = bestlv;
    __syncthreads();
    for (int o = 64; o > 0; o >>= 1) {
        if (t < o) {
            if (sBv[t + o] > sBv[t] || (sBv[t + o] == sBv[t] && sBi[t + o] < sBi[t])) {
                sBv[t] = sBv[t + o]; sBi[t] = sBi[t + o]; sLv[t] = sLv[t + o];
            }
        }
        __syncthreads();
    }
    if (t == 0) { outidx[row] = sBi[0]; outlv[row] = sLv[0]; }
}

// ======================= z_q gather =======================
__global__ void __launch_bounds__(256)
gather_zq_kernel(const float* __restrict__ P, const int* __restrict__ idx,
                 const float* __restrict__ b1, float* __restrict__ out) {
    int m = blockIdx.x;
    int c = threadIdx.x * 4;
    int4 id = *reinterpret_cast<const int4*>(&idx[m * 4]);
    float4 p0 = *reinterpret_cast<const float4*>(&P[((size_t)0 * kNE + id.x) * kD + c]);
    float4 p1 = *reinterpret_cast<const float4*>(&P[((size_t)1 * kNE + id.y) * kD + c]);
    float4 p2 = *reinterpret_cast<const float4*>(&P[((size_t)2 * kNE + id.z) * kD + c]);
    float4 p3 = *reinterpret_cast<const float4*>(&P[((size_t)3 * kNE + id.w) * kD + c]);
    float4 bb = *reinterpret_cast<const float4*>(&b1[c]);
    float4 v;
    v.x = ((p0.x + p1.x) + p2.x) + p3.x + bb.x;
    v.y = ((p0.y + p1.y) + p2.y) + p3.y + bb.y;
    v.z = ((p0.z + p1.z) + p2.z) + p3.z + bb.z;
    v.w = ((p0.w + p1.w) + p2.w) + p3.w + bb.w;
    size_t o = (size_t)m * kD + c;
    out[o + 0] = v.x; out[o + 1] = v.y; out[o + 2] = v.z; out[o + 3] = v.w;
}

// ------------------------- loss from winner lv: out[0] = 1.25 * sum(lv) / 2^24 -----------------
__global__ void __launch_bounds__(1024)
lvsum_kernel(const float* __restrict__ lv, float* __restrict__ out) {
    int t = threadIdx.x;
    double s = 0.0;
    for (int i = t; i < kMR; i += 1024) s += (double)lv[i];
    __shared__ double sd[1024];
    sd[t] = s;
    __syncthreads();
    for (int o = 512; o > 0; o >>= 1) {
        if (t < o) sd[t] += sd[t + o];
        __syncthreads();
    }
    if (t == 0) {
        float m = (float)(sd[0] / 16777216.0);
        out[0] = m + 0.25f * m;
    }
}

// ------------------------- launch (chunked gemm0 || argmax pipeline) -------------------------
extern "C" void kernel_launch(void* const* d_in, const int* in_sizes, int n_in,
                              void* d_out, int out_size) {
    const float* z  = (const float*)d_in[0];
    const float* W0 = (const float*)d_in[1];
    const float* b0 = (const float*)d_in[2];
    const float* W1 = (const float*)d_in[3];
    const float* b1 = (const float*)d_in[4];
    const float* E  = (const float*)d_in[5];
    float* out = (float*)d_out;

    float *p_cz, *p_esq, *p_esq_mm, *p_czsq, *p_P, *p_lv;
    int* p_idx;
    cudaGetSymbolAddress((void**)&p_cz, g_cz);
    cudaGetSymbolAddress((void**)&p_esq, g_esq);
    cudaGetSymbolAddress((void**)&p_esq_mm, g_esq_mm);
    cudaGetSymbolAddress((void**)&p_czsq, g_czsq);
    cudaGetSymbolAddress((void**)&p_idx, g_idx);
    cudaGetSymbolAddress((void**)&p_P, g_P);
    cudaGetSymbolAddress((void**)&p_lv, g_lv);

    static cudaStream_t sB = 0;
    static cudaEvent_t evFork, evEnd, evA[NCHUNK];
    static bool init_done = false;
    if (!init_done) {
        if (cudaStreamCreateWithFlags(&sB, cudaStreamNonBlocking) != cudaSuccess) sB = 0;
        cudaEventCreateWithFlags(&evFork, cudaEventDisableTiming);
        cudaEventCreateWithFlags(&evEnd, cudaEventDisableTiming);
        for (int c = 0; c < NCHUNK; c++)
            cudaEventCreateWithFlags(&evA[c], cudaEventDisableTiming);
        init_done = true;
    }

    int zoff = out_size - kM1 * kD;
    float* zq = out + (zoff > 0 ? zoff : 0);
    bool do_loss = (zoff >= 1);
    bool do_zq = (out_size >= kM1 * kD);

    // fork sB from the capture stream
    cudaEventRecord(evFork, 0);
    cudaStreamWaitEvent(sB, evFork, 0);

    // sB: codebook-side precomputes (independent of cz)
    pgemm_kernel<<<dim3(kD / 128, kNE / 128, kCH), 256, 0, sB>>>(E, W1, p_P);
    rowsq4_kernel<<<kNE / 32, 256, 0, sB>>>(E, p_esq);
    esq_minmax_kernel<<<1, 256, 0, sB>>>(p_esq, p_esq_mm);

    // stream0: gemm0 chunks; sB consumes each chunk (rowsq -> argmax -> gather)
    for (int c = 0; c < NCHUNK; c++) {
        gemm0_kernel<<<dim3(kD / 128, M1C / 128), 256>>>(
            z + (size_t)c * M1C * kD, W0, b0, p_cz + (size_t)c * M1C * kD, kD, kD);
        cudaEventRecord(evA[c], 0);
        cudaStreamWaitEvent(sB, evA[c], 0);
        rowsq4_kernel<<<MRC / 32, 256, 0, sB>>>(p_cz + (size_t)c * M1C * kD,
                                                p_czsq + (size_t)c * MRC);
        argmax3_kernel<<<MRC, 128, 0, sB>>>(p_cz + (size_t)c * M1C * kD, E,
                                            p_czsq + (size_t)c * MRC, p_esq, p_esq_mm,
                                            p_idx + (size_t)c * MRC,
                                            p_lv + (size_t)c * MRC, c * MRC);
        if (do_zq)
            gather_zq_kernel<<<M1C, 256, 0, sB>>>(p_P, p_idx + (size_t)c * MRC, b1,
                                                  zq + (size_t)c * M1C * kD);
    }
    if (do_loss)
        lvsum_kernel<<<1, 1024, 0, sB>>>(p_lv, out);

    // join sB back into the capture stream
    cudaEventRecord(evEnd, sB);
    cudaStreamWaitEvent(0, evEnd, 0);
}